// round 13
// baseline (speedup 1.0000x reference)
#include <cuda_runtime.h>
#include <cuda_bf16.h>
#include <math.h>
#include <stdint.h>

#define BB 64
#define TT 1024
#define FF 128
#define UU 256

typedef unsigned long long ull;

// ---------------------------------------------------------------------------
// Packed f32x2 helpers (sm_100+): two independent fp32 FMAs per instruction,
// exact fp32 arithmetic.
// ---------------------------------------------------------------------------
__device__ __forceinline__ void ffma2(ull &d, ull a, ull b) {
    asm("fma.rn.f32x2 %0, %1, %2, %0;" : "+l"(d) : "l"(a), "l"(b));
}
__device__ __forceinline__ ull packf2(float lo, float hi) {
    ull r;
    asm("mov.b64 %0, {%1, %2};" : "=l"(r) : "f"(lo), "f"(hi));
    return r;
}
__device__ __forceinline__ float f2lo(ull v) { return __uint_as_float((unsigned)v); }
__device__ __forceinline__ float f2hi(ull v) { return __uint_as_float((unsigned)(v >> 32)); }

// Fast tanh via MUFU.EX2 + MUFU.RCP (rel err ~1e-6 on this recurrence's range).
__device__ __forceinline__ float tanh_fast(float y) {
    float e = __expf(2.0f * y);
    return 1.0f - __fdividef(2.0f, e + 1.0f);
}

// ---------------------------------------------------------------------------
// Kernel 1: projection  h[t,b,u] = sum_f inputs[b,t,f] * R[f,u]  + bias[u]
// (bias folded here so the recurrence never touches it).
// Written into d_out ([T,B,U]); the recurrence kernel overwrites in place.
// Grid (2, B) = 128 CTAs (one wave), 256 threads. Each CTA: 512 t-rows in
// 16 chunks of 32; R filled into smem ONCE per CTA. Inputs double-buffered
// through registers.
// ---------------------------------------------------------------------------
#define PROJ_SMEM (128 * 1024 + 32 * 128 * 4)
#define ROWS_PER_CTA 512
#define CHUNKS (ROWS_PER_CTA / 32)

__global__ __launch_bounds__(256, 1)
void proj_kernel(const float* __restrict__ inp, const float* __restrict__ R,
                 const float* __restrict__ bias, float* __restrict__ out)
{
    extern __shared__ ull smem_p[];
    ull*   Rs  = smem_p;                    // 16384 ull: Rs[p*256+u] = (R[2p][u], R[2p+1][u])
    float* xin = (float*)(smem_p + 16384);  // 32 rows x 128 floats

    const int tid = threadIdx.x;
    const int b   = blockIdx.y;
    const int tb  = blockIdx.x * ROWS_PER_CTA;

    // Fill Rs once (coalesced over u).
    #pragma unroll 1
    for (int i = 0; i < 64; ++i) {
        Rs[i * 256 + tid] = packf2(R[(2 * i) * UU + tid], R[(2 * i + 1) * UU + tid]);
    }

    const float4* src = (const float4*)(inp + (size_t)b * TT * FF + (size_t)tb * FF);
    float4 pf[4];
    #pragma unroll
    for (int i = 0; i < 4; ++i) pf[i] = src[tid + i * 256];

    const int uu = tid & 63;
    const int rg = tid >> 6;
    const int u0 = uu * 4;
    const ull* xr = (const ull*)xin;

    const float4 bb = *(const float4*)(bias + u0);   // loop-invariant

    #pragma unroll 1
    for (int ch = 0; ch < CHUNKS; ++ch) {
        float4* dst = (float4*)xin;
        #pragma unroll
        for (int i = 0; i < 4; ++i) dst[tid + i * 256] = pf[i];
        __syncthreads();

        int chn = (ch + 1 < CHUNKS) ? ch + 1 : ch;
        #pragma unroll
        for (int i = 0; i < 4; ++i) pf[i] = src[chn * 1024 + tid + i * 256];

        ull acc[32];
        #pragma unroll
        for (int i = 0; i < 32; ++i) acc[i] = 0ull;

        #pragma unroll 4
        for (int p = 0; p < 64; ++p) {
            ull w0 = Rs[p * 256 + u0 + 0];
            ull w1 = Rs[p * 256 + u0 + 1];
            ull w2 = Rs[p * 256 + u0 + 2];
            ull w3 = Rs[p * 256 + u0 + 3];
            #pragma unroll
            for (int ri = 0; ri < 8; ++ri) {
                ull xv = xr[(rg * 8 + ri) * 64 + p];
                ffma2(acc[ri * 4 + 0], xv, w0);
                ffma2(acc[ri * 4 + 1], xv, w1);
                ffma2(acc[ri * 4 + 2], xv, w2);
                ffma2(acc[ri * 4 + 3], xv, w3);
            }
        }

        #pragma unroll
        for (int ri = 0; ri < 8; ++ri) {
            int t = tb + ch * 32 + rg * 8 + ri;
            float4 v;
            v.x = f2lo(acc[ri * 4 + 0]) + f2hi(acc[ri * 4 + 0]) + bb.x;
            v.y = f2lo(acc[ri * 4 + 1]) + f2hi(acc[ri * 4 + 1]) + bb.y;
            v.z = f2lo(acc[ri * 4 + 2]) + f2hi(acc[ri * 4 + 2]) + bb.z;
            v.w = f2lo(acc[ri * 4 + 3]) + f2hi(acc[ri * 4 + 3]) + bb.w;
            *(float4*)(out + (size_t)t * (BB * UU) + (size_t)b * UU + u0) = v;
        }
        __syncthreads();   // protect xin before next chunk's store
    }
}

// ---------------------------------------------------------------------------
// Kernel 2: recurrence, shuffle-reduce layout. 64 CTAs x 512 threads.
//   x_t = tanh(h[t] + x_{t-1} @ W)        (bias already folded into h)
// Warp w owns u-block [16w, 16w+16). Lane l = ks*4 + uq (ks=l>>2, uq=l&3):
//   u-cols U0..U0+3 with U0 = 16w + 4uq;  k in [32ks, 32ks+32) = 16 k-pairs:
//   pairs 0..11 -> registers (96 regs), pairs 12..15 -> smem (64 KB,
//   conflict-free LDS.128, identical slot scheme to R7).
// State in smem as 64 ulonglong2 chunks, i-major swizzled:
//   chunk ck (floats 4ck..4ck+3) stored at phys = (ck&7)*8 + (ck>>3),
//   so a warp's per-i read (8 distinct ks) covers one 128B row: 1 phase.
// Per step: FMA -> 3x shfl.bfly reduce (no partial array, no extra barrier)
//   -> lanes ks==0 finalize 4 u each (h add, tanh, state STS.128, out STG.128)
//   -> ONE __syncthreads.
// ---------------------------------------------------------------------------
#define REC_SMEM (64 * 1024 + 64 * 16)

__global__ __launch_bounds__(512, 1)
void rec_kernel(const float* __restrict__ W, const float* __restrict__ x0,
                float* __restrict__ out)
{
    extern __shared__ ull smem_r[];
    ulonglong2* Wsm2 = (ulonglong2*)smem_r;           // 8 slots * 512 = 64 KB
    ulonglong2* sx2  = (ulonglong2*)(smem_r + 8192);  // 64 chunks = 1 KB (swizzled)

    const int tid = threadIdx.x;
    const int b   = blockIdx.x;
    const int w   = tid >> 5;
    const int l   = tid & 31;
    const int ks  = l >> 2;                 // 0..7  k-split
    const int uq  = l & 3;                  // 0..3
    const int U0  = w * 16 + uq * 4;        // this thread's 4 u columns

    // --- Load W: k-pairs 16ks..16ks+15; 0-11 -> regs, 12-15 -> smem ---
    ull wreg[4][12];
    #pragma unroll
    for (int j = 0; j < 16; ++j) {
        int P = 16 * ks + j;                // global k-pair
        float4 va = *(const float4*)(W + (size_t)(2 * P)     * UU + U0);
        float4 vb = *(const float4*)(W + (size_t)(2 * P + 1) * UU + U0);
        ull w0 = packf2(va.x, vb.x);
        ull w1 = packf2(va.y, vb.y);
        ull w2 = packf2(va.z, vb.z);
        ull w3 = packf2(va.w, vb.w);
        if (j < 12) {
            wreg[0][j] = w0; wreg[1][j] = w1; wreg[2][j] = w2; wreg[3][j] = w3;
        } else {
            int q = j - 12;
            Wsm2[(q * 2 + 0) * 512 + tid] = make_ulonglong2(w0, w1);
            Wsm2[(q * 2 + 1) * 512 + tid] = make_ulonglong2(w2, w3);
        }
    }

    // --- Init state (swizzled): thread c<64 handles chunk c = floats 4c..4c+3 ---
    if (tid < 64) {
        float4 v = *(const float4*)(x0 + 4 * tid);
        int p = ((tid & 7) << 3) | (tid >> 3);
        sx2[p] = make_ulonglong2(packf2(v.x, v.y), packf2(v.z, v.w));
    }
    __syncthreads();

    const bool writer = (ks == 0);
    // Writer's state chunk c = U0/4 = w*4 + uq, at swizzled position:
    const int wc    = w * 4 + uq;
    const int wphys = ((wc & 7) << 3) | (wc >> 3);
    float* hop = out + (size_t)b * UU + U0;   // h read / x write, step stride B*U

    #pragma unroll 1
    for (int t = 0; t < TT; ++t) {
        // Prefetch h[t] (bias already folded in by proj); hides under FMA.
        float4 hreg = make_float4(0.f, 0.f, 0.f, 0.f);
        if (writer) hreg = *(const float4*)(hop + (size_t)t * (BB * UU));

        ull a0 = 0, a1 = 0, a2 = 0, a3 = 0;

        // k-pairs 0..11: register W. chunk i holds pairs 2i (.x), 2i+1 (.y)
        #pragma unroll
        for (int i = 0; i < 6; ++i) {
            ulonglong2 sp = sx2[i * 8 + ks];            // 1-phase LDS.128
            ffma2(a0, sp.x, wreg[0][2 * i]);     ffma2(a1, sp.x, wreg[1][2 * i]);
            ffma2(a2, sp.x, wreg[2][2 * i]);     ffma2(a3, sp.x, wreg[3][2 * i]);
            ffma2(a0, sp.y, wreg[0][2 * i + 1]); ffma2(a1, sp.y, wreg[1][2 * i + 1]);
            ffma2(a2, sp.y, wreg[2][2 * i + 1]); ffma2(a3, sp.y, wreg[3][2 * i + 1]);
        }
        // k-pairs 12..15: smem W (conflict-free), chunks 6 and 7
        {
            ulonglong2 sp = sx2[6 * 8 + ks];
            ulonglong2 wa0 = Wsm2[0 * 512 + tid];   // pair 12, u0/u1
            ulonglong2 wa1 = Wsm2[1 * 512 + tid];   // pair 12, u2/u3
            ffma2(a0, sp.x, wa0.x); ffma2(a1, sp.x, wa0.y);
            ffma2(a2, sp.x, wa1.x); ffma2(a3, sp.x, wa1.y);
            ulonglong2 wb0 = Wsm2[2 * 512 + tid];   // pair 13
            ulonglong2 wb1 = Wsm2[3 * 512 + tid];
            ffma2(a0, sp.y, wb0.x); ffma2(a1, sp.y, wb0.y);
            ffma2(a2, sp.y, wb1.x); ffma2(a3, sp.y, wb1.y);
        }
        {
            ulonglong2 sp = sx2[7 * 8 + ks];
            ulonglong2 wa0 = Wsm2[4 * 512 + tid];   // pair 14
            ulonglong2 wa1 = Wsm2[5 * 512 + tid];
            ffma2(a0, sp.x, wa0.x); ffma2(a1, sp.x, wa0.y);
            ffma2(a2, sp.x, wa1.x); ffma2(a3, sp.x, wa1.y);
            ulonglong2 wb0 = Wsm2[6 * 512 + tid];   // pair 15
            ulonglong2 wb1 = Wsm2[7 * 512 + tid];
            ffma2(a0, sp.y, wb0.x); ffma2(a1, sp.y, wb0.y);
            ffma2(a2, sp.y, wb1.x); ffma2(a3, sp.y, wb1.y);
        }

        // Collapse f32x2 halves, then butterfly-reduce over the 8 ks lanes.
        float s0 = f2lo(a0) + f2hi(a0);
        float s1 = f2lo(a1) + f2hi(a1);
        float s2 = f2lo(a2) + f2hi(a2);
        float s3 = f2lo(a3) + f2hi(a3);
        #pragma unroll
        for (int off = 4; off <= 16; off <<= 1) {
            s0 += __shfl_xor_sync(0xffffffffu, s0, off);
            s1 += __shfl_xor_sync(0xffffffffu, s1, off);
            s2 += __shfl_xor_sync(0xffffffffu, s2, off);
            s3 += __shfl_xor_sync(0xffffffffu, s3, off);
        }

        if (writer) {
            float4 xv;
            xv.x = tanh_fast(s0 + hreg.x);
            xv.y = tanh_fast(s1 + hreg.y);
            xv.z = tanh_fast(s2 + hreg.z);
            xv.w = tanh_fast(s3 + hreg.w);
            sx2[wphys] = make_ulonglong2(packf2(xv.x, xv.y), packf2(xv.z, xv.w));
            *(float4*)(hop + (size_t)t * (BB * UU)) = xv;   // overwrite h[t] with x_t
        }
        __syncthreads();   // state visible to all warps (BAR drains STS)
    }
}

// ---------------------------------------------------------------------------
// Launch. Inputs: inputs[B,T,F], R[F,U], W[U,U], bias[U], x0[U].
// Output: float32 states[T,B,U].
// ---------------------------------------------------------------------------
extern "C" void kernel_launch(void* const* d_in, const int* in_sizes, int n_in,
                              void* d_out, int out_size) {
    const float* inp  = (const float*)d_in[0];
    const float* R    = (const float*)d_in[1];
    const float* W    = (const float*)d_in[2];
    const float* bias = (const float*)d_in[3];
    const float* x0   = (const float*)d_in[4];
    float* out = (float*)d_out;

    cudaFuncSetAttribute(proj_kernel, cudaFuncAttributeMaxDynamicSharedMemorySize, PROJ_SMEM);
    cudaFuncSetAttribute(rec_kernel,  cudaFuncAttributeMaxDynamicSharedMemorySize, REC_SMEM);

    proj_kernel<<<dim3(TT / ROWS_PER_CTA, BB), 256, PROJ_SMEM>>>(inp, R, bias, out);
    rec_kernel<<<BB, 512, REC_SMEM>>>(W, x0, out);
}

// round 14
// speedup vs baseline: 1.2541x; 1.2541x over previous
#include <cuda_runtime.h>
#include <cuda_bf16.h>
#include <math.h>
#include <stdint.h>

#define BB 64
#define TT 1024
#define FF 128
#define UU 256

typedef unsigned long long ull;

// ---------------------------------------------------------------------------
// Packed f32x2 helpers (sm_100+): two independent fp32 FMAs per instruction,
// exact fp32 arithmetic.
// ---------------------------------------------------------------------------
__device__ __forceinline__ void ffma2(ull &d, ull a, ull b) {
    asm("fma.rn.f32x2 %0, %1, %2, %0;" : "+l"(d) : "l"(a), "l"(b));
}
__device__ __forceinline__ ull packf2(float lo, float hi) {
    ull r;
    asm("mov.b64 %0, {%1, %2};" : "=l"(r) : "f"(lo), "f"(hi));
    return r;
}
__device__ __forceinline__ float f2lo(ull v) { return __uint_as_float((unsigned)v); }
__device__ __forceinline__ float f2hi(ull v) { return __uint_as_float((unsigned)(v >> 32)); }

// Fast tanh via MUFU.EX2 + MUFU.RCP (rel err ~1e-6 on this recurrence's range).
__device__ __forceinline__ float tanh_fast(float y) {
    float e = __expf(2.0f * y);
    return 1.0f - __fdividef(2.0f, e + 1.0f);
}

// Named block barriers (512 participants). Non-finalizer warps ARRIVE on 1
// (non-blocking) and only block on 2 — halves their drain count per step.
__device__ __forceinline__ void bar_sync1()   { asm volatile("bar.sync 1, 512;"   ::: "memory"); }
__device__ __forceinline__ void bar_arrive1() { asm volatile("bar.arrive 1, 512;" ::: "memory"); }
__device__ __forceinline__ void bar_sync2()   { asm volatile("bar.sync 2, 512;"   ::: "memory"); }

// ---------------------------------------------------------------------------
// Kernel 1: projection  h[t,b,u] = sum_f inputs[b,t,f] * R[f,u] + bias[u]
// (bias folded here so the recurrence never touches it).
// Grid (2, B) = 128 CTAs, 256 threads. R filled into smem once per CTA;
// inputs double-buffered through registers. Inner loop now uses LDS.128
// exclusively: 12 load issues per 64 FFMA2 (was 24).
// ---------------------------------------------------------------------------
#define PROJ_SMEM (128 * 1024 + 32 * 128 * 4)
#define ROWS_PER_CTA 512
#define CHUNKS (ROWS_PER_CTA / 32)

__global__ __launch_bounds__(256, 1)
void proj_kernel(const float* __restrict__ inp, const float* __restrict__ R,
                 const float* __restrict__ bias, float* __restrict__ out)
{
    extern __shared__ ull smem_p[];
    ull*   Rs  = smem_p;                    // 16384 ull: Rs[p*256+u] = (R[2p][u], R[2p+1][u])
    float* xin = (float*)(smem_p + 16384);  // 32 rows x 128 floats

    const int tid = threadIdx.x;
    const int b   = blockIdx.y;
    const int tb  = blockIdx.x * ROWS_PER_CTA;

    // Fill Rs once (coalesced over u).
    #pragma unroll 1
    for (int i = 0; i < 64; ++i) {
        Rs[i * 256 + tid] = packf2(R[(2 * i) * UU + tid], R[(2 * i + 1) * UU + tid]);
    }

    const float4* src = (const float4*)(inp + (size_t)b * TT * FF + (size_t)tb * FF);
    float4 pf[4];
    #pragma unroll
    for (int i = 0; i < 4; ++i) pf[i] = src[tid + i * 256];

    const int uu = tid & 63;
    const int rg = tid >> 6;
    const int u0 = uu * 4;
    const ulonglong2* Rs2 = (const ulonglong2*)Rs;   // index = (p*256+u)/2
    const ulonglong2* xr2 = (const ulonglong2*)xin;  // index = row*32+pp -> f-pairs 2pp,2pp+1

    const float4 bb = *(const float4*)(bias + u0);   // loop-invariant

    #pragma unroll 1
    for (int ch = 0; ch < CHUNKS; ++ch) {
        float4* dst = (float4*)xin;
        #pragma unroll
        for (int i = 0; i < 4; ++i) dst[tid + i * 256] = pf[i];
        __syncthreads();

        int chn = (ch + 1 < CHUNKS) ? ch + 1 : ch;
        #pragma unroll
        for (int i = 0; i < 4; ++i) pf[i] = src[chn * 1024 + tid + i * 256];

        ull acc[32];
        #pragma unroll
        for (int i = 0; i < 32; ++i) acc[i] = 0ull;

        #pragma unroll 2
        for (int pp = 0; pp < 32; ++pp) {
            int p0 = 2 * pp, p1 = 2 * pp + 1;
            ulonglong2 wA01 = Rs2[(p0 * 256 + u0) >> 1];       // LDS.128: u0,u0+1
            ulonglong2 wA23 = Rs2[((p0 * 256 + u0) >> 1) + 1]; // u0+2,u0+3
            ulonglong2 wB01 = Rs2[(p1 * 256 + u0) >> 1];
            ulonglong2 wB23 = Rs2[((p1 * 256 + u0) >> 1) + 1];
            #pragma unroll
            for (int ri = 0; ri < 8; ++ri) {
                ulonglong2 xv = xr2[(rg * 8 + ri) * 32 + pp];  // broadcast LDS.128
                ffma2(acc[ri * 4 + 0], xv.x, wA01.x);
                ffma2(acc[ri * 4 + 1], xv.x, wA01.y);
                ffma2(acc[ri * 4 + 2], xv.x, wA23.x);
                ffma2(acc[ri * 4 + 3], xv.x, wA23.y);
                ffma2(acc[ri * 4 + 0], xv.y, wB01.x);
                ffma2(acc[ri * 4 + 1], xv.y, wB01.y);
                ffma2(acc[ri * 4 + 2], xv.y, wB23.x);
                ffma2(acc[ri * 4 + 3], xv.y, wB23.y);
            }
        }

        #pragma unroll
        for (int ri = 0; ri < 8; ++ri) {
            int t = tb + ch * 32 + rg * 8 + ri;
            float4 v;
            v.x = f2lo(acc[ri * 4 + 0]) + f2hi(acc[ri * 4 + 0]) + bb.x;
            v.y = f2lo(acc[ri * 4 + 1]) + f2hi(acc[ri * 4 + 1]) + bb.y;
            v.z = f2lo(acc[ri * 4 + 2]) + f2hi(acc[ri * 4 + 2]) + bb.z;
            v.w = f2lo(acc[ri * 4 + 3]) + f2hi(acc[ri * 4 + 3]) + bb.w;
            *(float4*)(out + (size_t)t * (BB * UU) + (size_t)b * UU + u0) = v;
        }
        __syncthreads();   // protect xin before next chunk's store
    }
}

// ---------------------------------------------------------------------------
// Kernel 2: recurrence — measured-best R7/R10 partition (96 W-regs + 64 KB
// smem W, 64 CTAs x 512 threads), plus:
//   * named-barrier split (non-finalizers block once per step, not twice)
//   * explicit load pipelining: state chunks rotate through 2 live regs,
//     W-smem LDS.128 issued one half-group ahead of use.
//   x_t = tanh(h[t] + x_{t-1} @ W)      (bias folded into h by proj)
// ---------------------------------------------------------------------------
#define REC_SMEM (64 * 1024 + 256 * 4 + 8 * 256 * 4)

__global__ __launch_bounds__(512, 1)
void rec_kernel(const float* __restrict__ W, const float* __restrict__ x0,
                float* __restrict__ out)
{
    extern __shared__ ull smem_r[];
    ulonglong2* Wsm2    = (ulonglong2*)smem_r;         // 8 slots * 512 ull2 = 64 KB
    float*      sxf     = (float*)(smem_r + 8192);     // 256 floats (state)
    float*      partial = sxf + 256;                   // 8 * 256 floats

    const int tid = threadIdx.x;
    const int b   = blockIdx.x;
    const int kq  = tid >> 6;        // 0..7
    const int u0  = (tid & 63) * 4;
    const int k0  = kq * 32;

    // --- Load W partition: 16 k-pairs; 0-11 -> regs, 12-15 -> smem ---
    ull wreg[4][12];
    #pragma unroll
    for (int p = 0; p < 16; ++p) {
        float4 va = *(const float4*)(W + (size_t)(k0 + 2 * p)     * UU + u0);
        float4 vb = *(const float4*)(W + (size_t)(k0 + 2 * p + 1) * UU + u0);
        ull w0 = packf2(va.x, vb.x);
        ull w1 = packf2(va.y, vb.y);
        ull w2 = packf2(va.z, vb.z);
        ull w3 = packf2(va.w, vb.w);
        if (p < 12) {
            wreg[0][p] = w0; wreg[1][p] = w1; wreg[2][p] = w2; wreg[3][p] = w3;
        } else {
            int q = p - 12;
            Wsm2[(q * 2 + 0) * 512 + tid] = make_ulonglong2(w0, w1);
            Wsm2[(q * 2 + 1) * 512 + tid] = make_ulonglong2(w2, w3);
        }
    }

    if (tid < 256) sxf[tid] = x0[tid];
    __syncthreads();

    float* outp = out + (size_t)b * UU + tid;                 // deref only tid<256
    const ulonglong2* sx2 = (const ulonglong2*)sxf + kq * 8;  // this kq's 16 pairs

    #pragma unroll 1
    for (int t = 0; t < TT; ++t) {
        // Prefetch h[t,b,u] (bias folded in); latency hides under FMA.
        float hreg = 0.f;
        if (tid < 256) hreg = outp[(size_t)t * (BB * UU)];

        ull acc0 = 0, acc1 = 0, acc2 = 0, acc3 = 0;

        // ---- pipelined state reads: rotate through 2 live regs ----
        ulonglong2 xpa = sx2[0];
        ulonglong2 xpb = sx2[1];

        // k-pairs 0..11: register W (chunks 0..5)
        #pragma unroll
        for (int i = 0; i < 6; ++i) {
            ulonglong2 cur = xpa;
            xpa = xpb;
            xpb = sx2[i + 2];                 // chunks up to 7 (used below)
            ffma2(acc0, cur.x, wreg[0][2 * i]);
            ffma2(acc1, cur.x, wreg[1][2 * i]);
            ffma2(acc2, cur.x, wreg[2][2 * i]);
            ffma2(acc3, cur.x, wreg[3][2 * i]);
            ffma2(acc0, cur.y, wreg[0][2 * i + 1]);
            ffma2(acc1, cur.y, wreg[1][2 * i + 1]);
            ffma2(acc2, cur.y, wreg[2][2 * i + 1]);
            ffma2(acc3, cur.y, wreg[3][2 * i + 1]);
        }
        // xpa = chunk 6, xpb = chunk 7.
        // k-pairs 12..15: smem W; issue each half-group's loads ahead of use.
        {
            ulonglong2 wa0 = Wsm2[0 * 512 + tid];   // pair 12
            ulonglong2 wa1 = Wsm2[1 * 512 + tid];
            ulonglong2 wb0 = Wsm2[2 * 512 + tid];   // pair 13
            ulonglong2 wb1 = Wsm2[3 * 512 + tid];
            ffma2(acc0, xpa.x, wa0.x); ffma2(acc1, xpa.x, wa0.y);
            ffma2(acc2, xpa.x, wa1.x); ffma2(acc3, xpa.x, wa1.y);
            ulonglong2 wc0 = Wsm2[4 * 512 + tid];   // pair 14 (prefetch)
            ulonglong2 wc1 = Wsm2[5 * 512 + tid];
            ffma2(acc0, xpa.y, wb0.x); ffma2(acc1, xpa.y, wb0.y);
            ffma2(acc2, xpa.y, wb1.x); ffma2(acc3, xpa.y, wb1.y);
            ulonglong2 wd0 = Wsm2[6 * 512 + tid];   // pair 15 (prefetch)
            ulonglong2 wd1 = Wsm2[7 * 512 + tid];
            ffma2(acc0, xpb.x, wc0.x); ffma2(acc1, xpb.x, wc0.y);
            ffma2(acc2, xpb.x, wc1.x); ffma2(acc3, xpb.x, wc1.y);
            ffma2(acc0, xpb.y, wd0.x); ffma2(acc1, xpb.y, wd0.y);
            ffma2(acc2, xpb.y, wd1.x); ffma2(acc3, xpb.y, wd1.y);
        }

        float4 ps;
        ps.x = f2lo(acc0) + f2hi(acc0);
        ps.y = f2lo(acc1) + f2hi(acc1);
        ps.z = f2lo(acc2) + f2hi(acc2);
        ps.w = f2lo(acc3) + f2hi(acc3);
        *(float4*)(partial + kq * 256 + u0) = ps;             // STS.128 conflict-free

        if (tid < 256) {
            bar_sync1();                                      // wait for all partials
            float s0 = partial[           tid] + partial[ 256 + tid];
            float s1 = partial[ 512 + tid] + partial[ 768 + tid];
            float s2 = partial[1024 + tid] + partial[1280 + tid];
            float s3 = partial[1536 + tid] + partial[1792 + tid];
            float y  = ((s0 + s1) + (s2 + s3)) + hreg;
            float x  = tanh_fast(y);
            sxf[tid] = x;                                     // new state
            outp[(size_t)t * (BB * UU)] = x;                  // overwrite h[t]
            bar_sync2();                                      // state visible to all
        } else {
            bar_arrive1();                                    // non-blocking
            bar_sync2();                                      // single wait per step
        }
    }
}

// ---------------------------------------------------------------------------
// Launch. Inputs: inputs[B,T,F], R[F,U], W[U,U], bias[U], x0[U].
// Output: float32 states[T,B,U].
// ---------------------------------------------------------------------------
extern "C" void kernel_launch(void* const* d_in, const int* in_sizes, int n_in,
                              void* d_out, int out_size) {
    const float* inp  = (const float*)d_in[0];
    const float* R    = (const float*)d_in[1];
    const float* W    = (const float*)d_in[2];
    const float* bias = (const float*)d_in[3];
    const float* x0   = (const float*)d_in[4];
    float* out = (float*)d_out;

    cudaFuncSetAttribute(proj_kernel, cudaFuncAttributeMaxDynamicSharedMemorySize, PROJ_SMEM);
    cudaFuncSetAttribute(rec_kernel,  cudaFuncAttributeMaxDynamicSharedMemorySize, REC_SMEM);

    proj_kernel<<<dim3(TT / ROWS_PER_CTA, BB), 256, PROJ_SMEM>>>(inp, R, bias, out);
    rec_kernel<<<BB, 512, REC_SMEM>>>(W, x0, out);
}

// round 15
// speedup vs baseline: 1.3657x; 1.0890x over previous
#include <cuda_runtime.h>
#include <cuda_bf16.h>
#include <math.h>
#include <stdint.h>

#define BB 64
#define TT 1024
#define FF 128
#define UU 256

typedef unsigned long long ull;

// Per-batch progress counters (chunks of 32 t-rows published by proj CTAs).
// Zero at module load; reset_kernel re-zeroes after every run so graph
// replays are deterministic.
__device__ int progress_g[BB];

// ---------------------------------------------------------------------------
// Packed f32x2 helpers (sm_100+): two independent fp32 FMAs per instruction,
// exact fp32 arithmetic.
// ---------------------------------------------------------------------------
__device__ __forceinline__ void ffma2(ull &d, ull a, ull b) {
    asm("fma.rn.f32x2 %0, %1, %2, %0;" : "+l"(d) : "l"(a), "l"(b));
}
__device__ __forceinline__ ull packf2(float lo, float hi) {
    ull r;
    asm("mov.b64 %0, {%1, %2};" : "=l"(r) : "f"(lo), "f"(hi));
    return r;
}
__device__ __forceinline__ float f2lo(ull v) { return __uint_as_float((unsigned)v); }
__device__ __forceinline__ float f2hi(ull v) { return __uint_as_float((unsigned)(v >> 32)); }

// Fast tanh via MUFU.EX2 + MUFU.RCP (rel err ~1e-6 on this recurrence's range).
__device__ __forceinline__ float tanh_fast(float y) {
    float e = __expf(2.0f * y);
    return 1.0f - __fdividef(2.0f, e + 1.0f);
}

// Acquire load for the progress poll (pairs with producer fence+atomic).
__device__ __forceinline__ int ld_acquire(const int* p) {
    int v;
    asm volatile("ld.acquire.gpu.global.s32 %0, [%1];" : "=r"(v) : "l"(p));
    return v;
}

// Named block barriers (512 participants) for the rec finalize split.
__device__ __forceinline__ void bar_sync1()   { asm volatile("bar.sync 1, 512;"   ::: "memory"); }
__device__ __forceinline__ void bar_arrive1() { asm volatile("bar.arrive 1, 512;" ::: "memory"); }
__device__ __forceinline__ void bar_sync2()   { asm volatile("bar.sync 2, 512;"   ::: "memory"); }

// ---------------------------------------------------------------------------
// Fused kernel, grid = 128 CTAs x 512 threads, all co-resident (1 CTA/SM):
//   CTA b in [0,64):    recurrence for batch b (consumes h from d_out)
//   CTA 64+b:           projection h[t,b,u] = inputs[b,t,:]@R + bias into
//                       d_out, publishing progress_g[b] per 32-row chunk.
// rec polls progress_g[b] once per 32 steps (acquire); proj releases with
// threadfence + syncthreads + atomicAdd. proj produces ~5x faster than rec
// consumes, so polls pass immediately after a ~5us initial skew.
// ---------------------------------------------------------------------------
#define FUSED_SMEM (128 * 1024 + 32 * 128 * 4)   /* proj role: 144 KB (max) */

__global__ __launch_bounds__(512, 1)
void fused_kernel(const float* __restrict__ inp, const float* __restrict__ R,
                  const float* __restrict__ W,   const float* __restrict__ bias,
                  const float* __restrict__ x0,  float* __restrict__ out)
{
    extern __shared__ ull smem[];
    const int tid = threadIdx.x;

    if (blockIdx.x >= 64) {
        // =================== PROJECTION ROLE ===================
        const int b = blockIdx.x - 64;
        ull*   Rs  = smem;                    // 16384 ull: Rs[p*256+u] = (R[2p][u], R[2p+1][u])
        float* xin = (float*)(smem + 16384);  // 32 rows x 128 floats

        // Fill Rs once (coalesced over u).
        #pragma unroll 1
        for (int i = 0; i < 32; ++i) {
            int e = i * 512 + tid;
            int u = e & 255, p = e >> 8;
            Rs[p * 256 + u] = packf2(R[(2 * p) * UU + u], R[(2 * p + 1) * UU + u]);
        }

        const float4* src = (const float4*)(inp + (size_t)b * TT * FF);
        float4 pf0 = src[tid], pf1 = src[512 + tid];

        const int uu = tid & 63;
        const int rg = tid >> 6;              // 0..7, rows rg*4..rg*4+3
        const int u0 = uu * 4;
        const ulonglong2* Rs2 = (const ulonglong2*)Rs;
        const ulonglong2* xr2 = (const ulonglong2*)xin;

        const float4 bb = *(const float4*)(bias + u0);

        #pragma unroll 1
        for (int ch = 0; ch < 32; ++ch) {
            float4* dst = (float4*)xin;
            dst[tid] = pf0; dst[512 + tid] = pf1;
            __syncthreads();

            int chn = (ch + 1 < 32) ? ch + 1 : ch;
            pf0 = src[chn * 1024 + tid];
            pf1 = src[chn * 1024 + 512 + tid];

            ull acc[16];
            #pragma unroll
            for (int i = 0; i < 16; ++i) acc[i] = 0ull;

            #pragma unroll 2
            for (int pp = 0; pp < 32; ++pp) {
                int p0 = 2 * pp, p1 = 2 * pp + 1;
                ulonglong2 wA01 = Rs2[(p0 * 256 + u0) >> 1];
                ulonglong2 wA23 = Rs2[((p0 * 256 + u0) >> 1) + 1];
                ulonglong2 wB01 = Rs2[(p1 * 256 + u0) >> 1];
                ulonglong2 wB23 = Rs2[((p1 * 256 + u0) >> 1) + 1];
                #pragma unroll
                for (int ri = 0; ri < 4; ++ri) {
                    ulonglong2 xv = xr2[(rg * 4 + ri) * 32 + pp];  // broadcast LDS.128
                    ffma2(acc[ri * 4 + 0], xv.x, wA01.x);
                    ffma2(acc[ri * 4 + 1], xv.x, wA01.y);
                    ffma2(acc[ri * 4 + 2], xv.x, wA23.x);
                    ffma2(acc[ri * 4 + 3], xv.x, wA23.y);
                    ffma2(acc[ri * 4 + 0], xv.y, wB01.x);
                    ffma2(acc[ri * 4 + 1], xv.y, wB01.y);
                    ffma2(acc[ri * 4 + 2], xv.y, wB23.x);
                    ffma2(acc[ri * 4 + 3], xv.y, wB23.y);
                }
            }

            #pragma unroll
            for (int ri = 0; ri < 4; ++ri) {
                int t = ch * 32 + rg * 4 + ri;
                float4 v;
                v.x = f2lo(acc[ri * 4 + 0]) + f2hi(acc[ri * 4 + 0]) + bb.x;
                v.y = f2lo(acc[ri * 4 + 1]) + f2hi(acc[ri * 4 + 1]) + bb.y;
                v.z = f2lo(acc[ri * 4 + 2]) + f2hi(acc[ri * 4 + 2]) + bb.z;
                v.w = f2lo(acc[ri * 4 + 3]) + f2hi(acc[ri * 4 + 3]) + bb.w;
                *(float4*)(out + (size_t)t * (BB * UU) + (size_t)b * UU + u0) = v;
            }

            // Publish chunk ch: release pattern (fence by all, bar, one atomic).
            __threadfence();
            __syncthreads();
            if (tid == 0) atomicAdd(&progress_g[b], 1);
        }
        return;
    }

    // =================== RECURRENCE ROLE ===================
    const int b = blockIdx.x;
    ulonglong2* Wsm2    = (ulonglong2*)smem;           // 8 slots * 512 ull2 = 64 KB
    float*      sxf     = (float*)(smem + 8192);       // 256 floats (state)
    float*      partial = sxf + 256;                   // 8 * 256 floats

    const int kq  = tid >> 6;        // 0..7
    const int u0  = (tid & 63) * 4;
    const int k0  = kq * 32;

    // --- Load W partition: 16 k-pairs; 0-11 -> regs, 12-15 -> smem ---
    ull wreg[4][12];
    #pragma unroll
    for (int p = 0; p < 16; ++p) {
        float4 va = *(const float4*)(W + (size_t)(k0 + 2 * p)     * UU + u0);
        float4 vb = *(const float4*)(W + (size_t)(k0 + 2 * p + 1) * UU + u0);
        ull w0 = packf2(va.x, vb.x);
        ull w1 = packf2(va.y, vb.y);
        ull w2 = packf2(va.z, vb.z);
        ull w3 = packf2(va.w, vb.w);
        if (p < 12) {
            wreg[0][p] = w0; wreg[1][p] = w1; wreg[2][p] = w2; wreg[3][p] = w3;
        } else {
            int q = p - 12;
            Wsm2[(q * 2 + 0) * 512 + tid] = make_ulonglong2(w0, w1);
            Wsm2[(q * 2 + 1) * 512 + tid] = make_ulonglong2(w2, w3);
        }
    }

    if (tid < 256) sxf[tid] = x0[tid];
    __syncthreads();

    float* outp = out + (size_t)b * UU + tid;                 // deref only tid<256
    const ulonglong2* sx2 = (const ulonglong2*)sxf + kq * 8;  // this kq's 16 pairs

    #pragma unroll 1
    for (int t = 0; t < TT; ++t) {
        // Gate on proj progress once per 32-step chunk (acquire).
        if ((t & 31) == 0) {
            int need = (t >> 5) + 1;
            while (ld_acquire(&progress_g[b]) < need) { }
        }

        // Prefetch h[t,b,u] (bias folded in); latency hides under FMA.
        float hreg = 0.f;
        if (tid < 256) hreg = outp[(size_t)t * (BB * UU)];

        ull acc0 = 0, acc1 = 0, acc2 = 0, acc3 = 0;

        // ---- pipelined state reads: rotate through 2 live regs ----
        ulonglong2 xpa = sx2[0];
        ulonglong2 xpb = sx2[1];

        // k-pairs 0..11: register W (chunks 0..5)
        #pragma unroll
        for (int i = 0; i < 6; ++i) {
            ulonglong2 cur = xpa;
            xpa = xpb;
            xpb = sx2[i + 2];
            ffma2(acc0, cur.x, wreg[0][2 * i]);
            ffma2(acc1, cur.x, wreg[1][2 * i]);
            ffma2(acc2, cur.x, wreg[2][2 * i]);
            ffma2(acc3, cur.x, wreg[3][2 * i]);
            ffma2(acc0, cur.y, wreg[0][2 * i + 1]);
            ffma2(acc1, cur.y, wreg[1][2 * i + 1]);
            ffma2(acc2, cur.y, wreg[2][2 * i + 1]);
            ffma2(acc3, cur.y, wreg[3][2 * i + 1]);
        }
        // xpa = chunk 6, xpb = chunk 7.
        // k-pairs 12..15: smem W; loads issued a half-group ahead of use.
        {
            ulonglong2 wa0 = Wsm2[0 * 512 + tid];
            ulonglong2 wa1 = Wsm2[1 * 512 + tid];
            ulonglong2 wb0 = Wsm2[2 * 512 + tid];
            ulonglong2 wb1 = Wsm2[3 * 512 + tid];
            ffma2(acc0, xpa.x, wa0.x); ffma2(acc1, xpa.x, wa0.y);
            ffma2(acc2, xpa.x, wa1.x); ffma2(acc3, xpa.x, wa1.y);
            ulonglong2 wc0 = Wsm2[4 * 512 + tid];
            ulonglong2 wc1 = Wsm2[5 * 512 + tid];
            ffma2(acc0, xpa.y, wb0.x); ffma2(acc1, xpa.y, wb0.y);
            ffma2(acc2, xpa.y, wb1.x); ffma2(acc3, xpa.y, wb1.y);
            ulonglong2 wd0 = Wsm2[6 * 512 + tid];
            ulonglong2 wd1 = Wsm2[7 * 512 + tid];
            ffma2(acc0, xpb.x, wc0.x); ffma2(acc1, xpb.x, wc0.y);
            ffma2(acc2, xpb.x, wc1.x); ffma2(acc3, xpb.x, wc1.y);
            ffma2(acc0, xpb.y, wd0.x); ffma2(acc1, xpb.y, wd0.y);
            ffma2(acc2, xpb.y, wd1.x); ffma2(acc3, xpb.y, wd1.y);
        }

        float4 ps;
        ps.x = f2lo(acc0) + f2hi(acc0);
        ps.y = f2lo(acc1) + f2hi(acc1);
        ps.z = f2lo(acc2) + f2hi(acc2);
        ps.w = f2lo(acc3) + f2hi(acc3);
        *(float4*)(partial + kq * 256 + u0) = ps;             // STS.128 conflict-free

        if (tid < 256) {
            bar_sync1();                                      // wait for all partials
            float s0 = partial[           tid] + partial[ 256 + tid];
            float s1 = partial[ 512 + tid] + partial[ 768 + tid];
            float s2 = partial[1024 + tid] + partial[1280 + tid];
            float s3 = partial[1536 + tid] + partial[1792 + tid];
            float y  = ((s0 + s1) + (s2 + s3)) + hreg;
            float x  = tanh_fast(y);
            sxf[tid] = x;                                     // new state
            outp[(size_t)t * (BB * UU)] = x;                  // overwrite h[t]
            bar_sync2();                                      // state visible to all
        } else {
            bar_arrive1();                                    // non-blocking
            bar_sync2();                                      // single wait per step
        }
    }
}

// Reset progress counters so every run (and every graph replay) starts at 0.
__global__ void reset_kernel() {
    if (threadIdx.x < BB) progress_g[threadIdx.x] = 0;
}

// ---------------------------------------------------------------------------
// Launch. Inputs: inputs[B,T,F], R[F,U], W[U,U], bias[U], x0[U].
// Output: float32 states[T,B,U]. One fused 128-CTA kernel + tiny reset.
// ---------------------------------------------------------------------------
extern "C" void kernel_launch(void* const* d_in, const int* in_sizes, int n_in,
                              void* d_out, int out_size) {
    const float* inp  = (const float*)d_in[0];
    const float* R    = (const float*)d_in[1];
    const float* W    = (const float*)d_in[2];
    const float* bias = (const float*)d_in[3];
    const float* x0   = (const float*)d_in[4];
    float* out = (float*)d_out;

    cudaFuncSetAttribute(fused_kernel, cudaFuncAttributeMaxDynamicSharedMemorySize, FUSED_SMEM);

    fused_kernel<<<2 * BB, 512, FUSED_SMEM>>>(inp, R, W, bias, x0, out);
    reset_kernel<<<1, 64>>>();
}